// round 3
// baseline (speedup 1.0000x reference)
#include <cuda_runtime.h>
#include <math.h>

#define BB 8
#define NN 16384
#define DD 768
#define RR 3
#define NEXP 4
#define HH 128

// ---- scratch (device globals; no allocation allowed) ----
__device__ float g_xr[BB * NN * RR];        // (B,N,R) proj-down result
__device__ float g_part[16384 * RR];        // per-block partial sums for mean
__device__ float g_G[BB * NEXP];            // gate weights
__device__ float g_mixed[BB * NN * RR];     // expert-mixed result

// ============================================================
// Kernel 1: xr = x @ Wd + bd   (+ per-block partial sums for mean)
// 8 warps/block, 1 row per warp. Wd transposed into smem for
// conflict-free float4 LDS.
// ============================================================
__global__ void k_down(const float* __restrict__ x,
                       const float* __restrict__ Wd,
                       const float* __restrict__ bd) {
    __shared__ float sW[3 * DD];   // [r][e] transposed
    __shared__ float sP[8][3];
    int tid = threadIdx.x;
    for (int i = tid; i < DD * RR; i += 256) {
        int e = i / RR, r = i % RR;
        sW[r * DD + e] = Wd[i];
    }
    __syncthreads();

    int warp = tid >> 5, lane = tid & 31;
    long row = (long)blockIdx.x * 8 + warp;
    const float4* xp = (const float4*)(x + row * DD);
    const float4* w0 = (const float4*)(sW);
    const float4* w1 = (const float4*)(sW + DD);
    const float4* w2 = (const float4*)(sW + 2 * DD);

    float a0 = 0.f, a1 = 0.f, a2 = 0.f;
#pragma unroll
    for (int c = 0; c < 6; c++) {
        int e4 = lane + c * 32;           // 192 float4 per row
        float4 v = xp[e4];
        float4 q0 = w0[e4], q1 = w1[e4], q2 = w2[e4];
        a0 += v.x * q0.x + v.y * q0.y + v.z * q0.z + v.w * q0.w;
        a1 += v.x * q1.x + v.y * q1.y + v.z * q1.z + v.w * q1.w;
        a2 += v.x * q2.x + v.y * q2.y + v.z * q2.z + v.w * q2.w;
    }
#pragma unroll
    for (int o = 16; o; o >>= 1) {
        a0 += __shfl_xor_sync(0xffffffffu, a0, o);
        a1 += __shfl_xor_sync(0xffffffffu, a1, o);
        a2 += __shfl_xor_sync(0xffffffffu, a2, o);
    }
    if (lane == 0) {
        a0 += bd[0]; a1 += bd[1]; a2 += bd[2];
        g_xr[row * 3 + 0] = a0;
        g_xr[row * 3 + 1] = a1;
        g_xr[row * 3 + 2] = a2;
        sP[warp][0] = a0; sP[warp][1] = a1; sP[warp][2] = a2;
    }
    __syncthreads();
    if (tid < 3) {
        float s = 0.f;
#pragma unroll
        for (int w = 0; w < 8; w++) s += sP[w][tid];
        g_part[blockIdx.x * 3 + tid] = s;
    }
}

// ============================================================
// Kernel 2: reduce partials -> xa, compute gating -> g_G.
// One block, 768 threads. Deterministic tree reductions.
// ============================================================
__global__ void k_gate(const float* __restrict__ noise,
                       const float* __restrict__ Wg,
                       const float* __restrict__ Wn) {
    __shared__ float xa[BB][RR];
    int tid = threadIdx.x;
    int w = tid >> 5, lane = tid & 31;
    if (w < BB * RR) {
        int b = w / RR, r = w % RR;
        float s = 0.f;
        for (int i = lane; i < 2048; i += 32)
            s += g_part[(b * 2048 + i) * 3 + r];
#pragma unroll
        for (int o = 16; o; o >>= 1) s += __shfl_xor_sync(0xffffffffu, s, o);
        if (lane == 0) xa[b][r] = s / (float)NN;
    }
    __syncthreads();
    if (tid < BB) {
        int b = tid;
        float h[NEXP];
#pragma unroll
        for (int e = 0; e < NEXP; e++) {
            float hg = 0.f, hn = 0.f;
#pragma unroll
            for (int r = 0; r < RR; r++) {
                hg += xa[b][r] * Wg[r * NEXP + e];
                hn += xa[b][r] * Wn[r * NEXP + e];
            }
            // stable softplus = max(x,0) + log1p(exp(-|x|))
            float sp = fmaxf(hn, 0.f) + log1pf(expf(-fabsf(hn)));
            h[e] = hg + noise[b * NEXP + e] * sp;
        }
        int i1 = 0;
#pragma unroll
        for (int e = 1; e < NEXP; e++) if (h[e] > h[i1]) i1 = e;
        int i2 = -1;
#pragma unroll
        for (int e = 0; e < NEXP; e++) {
            if (e == i1) continue;
            if (i2 < 0 || h[e] > h[i2]) i2 = e;
        }
        float d = expf(h[i2] - h[i1]);
        float denom = 1.f + d;
#pragma unroll
        for (int e = 0; e < NEXP; e++) g_G[b * NEXP + e] = 0.f;
        g_G[b * NEXP + i1] = 1.f / denom;
        g_G[b * NEXP + i2] = d / denom;
    }
}

// ============================================================
// Kernel 3: experts. One block per (b,r). 512 threads.
// Full 128x128 tile in SMEM; downsample -> 3x3 dwconv -> upsample,
// accumulate gate-weighted in registers (32 px/thread, fully
// unrolled so acc[] stays in registers — no local-mem spill).
// Bilinear (half-pixel, no antialias) == clamped lerp for these sizes.
// ============================================================
__global__ void k_experts(const float* __restrict__ dwk,
                          const float* __restrict__ dwb) {
    int b = blockIdx.x / RR, r = blockIdx.x % RR;
    extern __shared__ float sm[];
    float* A  = sm;                 // 128 x 129
    float* Dn = A + 128 * 129;      // up to 64 x 65
    float* C  = Dn + 64 * 65;       // up to 64 x 65
    int tid = threadIdx.x;          // 512

    float kk[9];
#pragma unroll
    for (int i = 0; i < 9; i++) kk[i] = dwk[r * 9 + i];
    float bias = dwb[r];
    float g0 = g_G[b * 4 + 0];
    float gj_all[4];
#pragma unroll
    for (int e = 0; e < 4; e++) gj_all[e] = g_G[b * 4 + e];

    for (int p = tid; p < HH * HH; p += 512)
        A[(p >> 7) * 129 + (p & 127)] = g_xr[((long)b * NN + p) * 3 + r];
    __syncthreads();

    float acc[32];
    // ---- scale 0: full-res conv ----
#pragma unroll
    for (int i = 0; i < 32; i++) {
        int p = tid + i * 512;
        int y = p >> 7, xx = p & 127;
        float s = bias;
#pragma unroll
        for (int dy = -1; dy <= 1; dy++) {
            int yy = y + dy;
            if (yy < 0 || yy >= 128) continue;
#pragma unroll
            for (int dx = -1; dx <= 1; dx++) {
                int xc = xx + dx;
                if (xc < 0 || xc >= 128) continue;
                s += A[yy * 129 + xc] * kk[(dy + 1) * 3 + (dx + 1)];
            }
        }
        acc[i] = g0 * s;
    }

    // ---- scales 1..3 ----
    for (int j = 1; j <= 3; j++) {
        int f = 1 << j;
        int ssz = 128 >> j;
        __syncthreads();  // prior C reads complete before rewriting Dn/C
        // downsample: exact 2-tap average at (f*i + f/2 - 1, +1) per axis
        for (int idx = tid; idx < ssz * ssz; idx += 512) {
            int y = idx / ssz, xx = idx % ssz;
            int ty = f * y + (f >> 1) - 1;
            int tx = f * xx + (f >> 1) - 1;
            Dn[y * 65 + xx] = 0.25f * (A[ty * 129 + tx] + A[ty * 129 + tx + 1] +
                                       A[(ty + 1) * 129 + tx] + A[(ty + 1) * 129 + tx + 1]);
        }
        __syncthreads();
        // 3x3 dwconv with zero pad on ssz x ssz
        for (int idx = tid; idx < ssz * ssz; idx += 512) {
            int y = idx / ssz, xx = idx % ssz;
            float s = bias;
#pragma unroll
            for (int dy = -1; dy <= 1; dy++) {
                int yy = y + dy;
                if (yy < 0 || yy >= ssz) continue;
#pragma unroll
                for (int dx = -1; dx <= 1; dx++) {
                    int xc = xx + dx;
                    if (xc < 0 || xc >= ssz) continue;
                    s += Dn[yy * 65 + xc] * kk[(dy + 1) * 3 + (dx + 1)];
                }
            }
            C[y * 65 + xx] = s;
        }
        __syncthreads();
        // upsample (clamped bilinear) + gate-weighted accumulate
        float inv = (float)ssz / 128.0f;
        float gj = gj_all[j];
#pragma unroll
        for (int i = 0; i < 32; i++) {
            int p = tid + i * 512;
            int y = p >> 7, xx = p & 127;
            float sy = (y + 0.5f) * inv - 0.5f;
            int iy = (int)floorf(sy);
            float wy = sy - (float)iy;
            int y0 = iy < 0 ? 0 : iy;
            int y1 = iy + 1 > ssz - 1 ? ssz - 1 : iy + 1;
            float sx = (xx + 0.5f) * inv - 0.5f;
            int ix = (int)floorf(sx);
            float wx = sx - (float)ix;
            int x0 = ix < 0 ? 0 : ix;
            int x1 = ix + 1 > ssz - 1 ? ssz - 1 : ix + 1;
            float v = (1.f - wy) * ((1.f - wx) * C[y0 * 65 + x0] + wx * C[y0 * 65 + x1]) +
                      wy * ((1.f - wx) * C[y1 * 65 + x0] + wx * C[y1 * 65 + x1]);
            acc[i] += gj * v;
        }
    }

#pragma unroll
    for (int i = 0; i < 32; i++) {
        int p = tid + i * 512;
        g_mixed[((long)b * NN + p) * 3 + r] = acc[i];
    }
}

// ============================================================
// Kernel 4: out = x + mixed @ Wu + bu.   192 threads, 8 rows/block.
// ============================================================
__global__ void k_up(const float* __restrict__ x,
                     const float* __restrict__ Wu,
                     const float* __restrict__ bu,
                     float* __restrict__ out) {
    int tid = threadIdx.x;  // 192 -> one float4 column each
    float4 u0 = ((const float4*)(Wu))[tid];
    float4 u1 = ((const float4*)(Wu + DD))[tid];
    float4 u2 = ((const float4*)(Wu + 2 * DD))[tid];
    float4 bb = ((const float4*)bu)[tid];
    long row0 = (long)blockIdx.x * 8;
#pragma unroll
    for (int rr = 0; rr < 8; rr++) {
        long row = row0 + rr;
        float m0 = __ldg(&g_mixed[row * 3 + 0]);
        float m1 = __ldg(&g_mixed[row * 3 + 1]);
        float m2 = __ldg(&g_mixed[row * 3 + 2]);
        float4 xv = ((const float4*)(x + row * DD))[tid];
        float4 o;
        o.x = xv.x + m0 * u0.x + m1 * u1.x + m2 * u2.x + bb.x;
        o.y = xv.y + m0 * u0.y + m1 * u1.y + m2 * u2.y + bb.y;
        o.z = xv.z + m0 * u0.z + m1 * u1.z + m2 * u2.z + bb.z;
        o.w = xv.w + m0 * u0.w + m1 * u1.w + m2 * u2.w + bb.w;
        ((float4*)(out + row * DD))[tid] = o;
    }
}

extern "C" void kernel_launch(void* const* d_in, const int* in_sizes, int n_in,
                              void* d_out, int out_size) {
    const float* x     = (const float*)d_in[0];
    const float* noise = (const float*)d_in[1];
    const float* Wd    = (const float*)d_in[2];
    const float* bd    = (const float*)d_in[3];
    const float* Wu    = (const float*)d_in[4];
    const float* bu    = (const float*)d_in[5];
    const float* Wg    = (const float*)d_in[6];
    const float* Wn    = (const float*)d_in[7];
    const float* dwk   = (const float*)d_in[8];
    const float* dwb   = (const float*)d_in[9];
    float* out = (float*)d_out;

    // idempotent host-side attribute (not a stream op; capture-safe)
    size_t smem = (128 * 129 + 2 * 64 * 65) * sizeof(float);  // 99328 B
    cudaFuncSetAttribute(k_experts, cudaFuncAttributeMaxDynamicSharedMemorySize, (int)smem);

    k_down<<<16384, 256>>>(x, Wd, bd);
    k_gate<<<1, 768>>>(noise, Wg, Wn);
    k_experts<<<BB * RR, 512, smem>>>(dwk, dwb);
    k_up<<<16384, 192>>>(x, Wu, bu, out);
}